// round 13
// baseline (speedup 1.0000x reference)
#include <cuda_runtime.h>
#include <cuda_fp16.h>
#include <cstdint>
#include <math.h>

// ============================================================================
// AutoEncoder via mma.sync (HMMA fp16), single-precision fp16 operands:
//   D = A_fp16 @ W_fp16 + bias (fp32 accum). 1 MMA per tile.
// R12: halved MMA work + halved A traffic vs R10's 2-term scheme.
// ============================================================================

#define BATCH 8192

__device__ __forceinline__ uint32_t smem_u32(const void* p) {
    uint32_t a;
    asm("{ .reg .u64 t; cvta.to.shared.u64 t, %1; cvt.u32.u64 %0, t; }"
        : "=r"(a) : "l"(p));
    return a;
}
__device__ __forceinline__ void cp_async16(uint32_t dst, const void* src) {
    asm volatile("cp.async.cg.shared.global [%0], [%1], 16;" :: "r"(dst), "l"(src));
}
__device__ __forceinline__ void cp_commit() {
    asm volatile("cp.async.commit_group;" ::: "memory");
}
template <int N> __device__ __forceinline__ void cp_wait() {
    asm volatile("cp.async.wait_group %0;" :: "n"(N) : "memory");
}
__device__ __forceinline__ void ldsm4(uint32_t* r, uint32_t a) {
    asm volatile("ldmatrix.sync.aligned.m8n8.x4.shared.b16 {%0,%1,%2,%3}, [%4];"
                 : "=r"(r[0]), "=r"(r[1]), "=r"(r[2]), "=r"(r[3]) : "r"(a));
}
__device__ __forceinline__ void mma16816(float* d, const uint32_t* a, const uint32_t* b) {
    asm volatile("mma.sync.aligned.m16n8k16.row.col.f32.f16.f16.f32 "
                 "{%0,%1,%2,%3}, {%4,%5,%6,%7}, {%8,%9}, {%0,%1,%2,%3};"
                 : "+f"(d[0]), "+f"(d[1]), "+f"(d[2]), "+f"(d[3])
                 : "r"(a[0]), "r"(a[1]), "r"(a[2]), "r"(a[3]),
                   "r"(b[0]), "r"(b[1]));
}
// 64B logical rows packed pairwise into 128B atoms + SW128 XOR swizzle.
__device__ __forceinline__ uint32_t tile_off(int r, int c) {
    uint32_t o = ((uint32_t)(r >> 1) << 7) + ((uint32_t)(r & 1) << 6) +
                 ((uint32_t)c << 4);
    return o ^ ((o >> 3) & 0x70);
}

// ---------------------------------------------------------------------------
// Device global scratch
// ---------------------------------------------------------------------------
__device__ __align__(16) __half g_bufA[(size_t)BATCH * 2048];
__device__ __align__(16) __half g_bufB[(size_t)BATCH * 2048];
__device__ __align__(16) __half g_ctrl[(size_t)BATCH * 64];

#define OFF_We1 0u
#define OFF_We2 (OFF_We1 + 2048u*1024u)
#define OFF_We3 (OFF_We2 + 2048u*2048u)
#define OFF_Wd1 (OFF_We3 + 64u*2048u)
#define OFF_Wd2 (OFF_Wd1 + 2048u*64u)
#define OFF_Wd3 (OFF_Wd2 + 2048u*2048u)
#define W_TOTAL (OFF_Wd3 + 1024u*2048u)
__device__ __align__(16) __half g_W[W_TOTAL];

// ---------------------------------------------------------------------------
// Fused prep: ONE launch. z=0: convert x to fp16; z=1..6: transpose weights
// to fp16.
// ---------------------------------------------------------------------------
__global__ void prep_all(const float* __restrict__ x,
                         __half* __restrict__ xh,
                         const float* We1, const float* We2, const float* We3,
                         const float* Wd1, const float* Wd2, const float* Wd3,
                         __half* __restrict__ W)
{
    const int z = blockIdx.z;
    if (z == 0) {
        int tid = threadIdx.y * 32 + threadIdx.x;
        int bid = blockIdx.y * 64 + blockIdx.x;
        int base = (bid * 256 + tid) * 2;
#pragma unroll
        for (int u = 0; u < 2; u++) {
            int i = base + u;
            float4 v = reinterpret_cast<const float4*>(x)[i];
            __half2 p0 = __halves2half2(__float2half_rn(v.x), __float2half_rn(v.y));
            __half2 p1 = __halves2half2(__float2half_rn(v.z), __float2half_rn(v.w));
            reinterpret_cast<__half2*>(xh)[i * 2 + 0] = p0;
            reinterpret_cast<__half2*>(xh)[i * 2 + 1] = p1;
        }
        return;
    }
    const float* Wi; uint32_t off; int K, N;
    switch (z) {
        case 1: Wi = We1; off = OFF_We1; K = 1024; N = 2048; break;
        case 2: Wi = We2; off = OFF_We2; K = 2048; N = 2048; break;
        case 3: Wi = We3; off = OFF_We3; K = 2048; N = 64;   break;
        case 4: Wi = Wd1; off = OFF_Wd1; K = 64;   N = 2048; break;
        case 5: Wi = Wd2; off = OFF_Wd2; K = 2048; N = 2048; break;
        default:Wi = Wd3; off = OFF_Wd3; K = 2048; N = 1024; break;
    }
    int k0 = blockIdx.x * 32, n0 = blockIdx.y * 32;
    if (k0 >= K || n0 >= N) return;
    __shared__ float t[32][33];
    int tx = threadIdx.x, ty = threadIdx.y;
    for (int r = ty; r < 32; r += 8)
        t[r][tx] = Wi[(size_t)(k0 + r) * N + n0 + tx];
    __syncthreads();
    __half* T = W + off;
    for (int r = ty; r < 32; r += 8) {
        size_t o = (size_t)(n0 + r) * K + k0 + tx;
        T[o] = __float2half_rn(t[tx][r]);
    }
}

// ---------------------------------------------------------------------------
// mma.sync fp16 GEMM: C = act(A @ W^T + bias), fp32 accumulate.
// 4-stage ring, 1 sync/iter, up to 3 CTAs/SM.
// OUTMODE: 0 = f32 only, 1 = fp16 only, 2 = both
// ---------------------------------------------------------------------------
template <int BM, int BN, int WARPS_M, int WARPS_N, int STAGES, int MINB, int OUTMODE>
__global__ __launch_bounds__(WARPS_M * WARPS_N * 32, MINB)
void gemm_mma(const __half* __restrict__ A,
              const __half* __restrict__ B,
              const float* __restrict__ bias,
              float* __restrict__ Cf,
              __half* __restrict__ Ch,
              int N, int K, int act)
{
    constexpr int THREADS = WARPS_M * WARPS_N * 32;
    constexpr int BK = 32;
    constexpr int WM = BM / WARPS_M, WN = BN / WARPS_N;
    constexpr int MW = WM / 16, NW = WN / 8;
    constexpr int ASZ = BM * 64;           // bytes per stage: A (32 fp16/row)
    constexpr int BSZ = BN * 64;
    constexpr int SSZ = ASZ + BSZ;

    extern __shared__ __align__(128) char sm[];
    const uint32_t sb = smem_u32(sm);
    const int tid = threadIdx.x, wid = tid >> 5, lid = tid & 31;
    const int row0 = blockIdx.y * BM, col0 = blockIdx.x * BN;
    const int KT = K / BK;

    const int wm0 = (wid % WARPS_M) * WM;
    const int wn0 = (wid / WARPS_M) * WN;
    const int mat = lid >> 3, mr = lid & 7;

    float acc[MW][NW][4];
#pragma unroll
    for (int i = 0; i < MW; i++)
#pragma unroll
        for (int j = 0; j < NW; j++)
#pragma unroll
            for (int q = 0; q < 4; q++) acc[i][j][q] = 0.0f;

    auto load_stage = [&](int kt, int s) {
        const uint32_t st = sb + s * SSZ;
        const int k0 = kt * BK;
#pragma unroll
        for (int ch = tid; ch < BM * 4; ch += THREADS) {
            int r = ch >> 2, c = ch & 3;
            size_t g = (size_t)(row0 + r) * K + k0 + c * 8;
            cp_async16(st + tile_off(r, c), A + g);
        }
#pragma unroll
        for (int ch = tid; ch < BN * 4; ch += THREADS) {
            int r = ch >> 2, c = ch & 3;
            size_t g = (size_t)(col0 + r) * K + k0 + c * 8;
            cp_async16(st + ASZ + tile_off(r, c), B + g);
        }
    };

    int arow[MW], brow[NW / 2];
#pragma unroll
    for (int i = 0; i < MW; i++) arow[i] = wm0 + i * 16 + (mat & 1) * 8 + mr;
#pragma unroll
    for (int j = 0; j < NW / 2; j++) brow[j] = wn0 + j * 16 + (mat >> 1) * 8 + mr;

#pragma unroll
    for (int p = 0; p < STAGES - 1; p++) {
        if (p < KT) load_stage(p, p);
        cp_commit();
    }

    for (int kt = 0; kt < KT; kt++) {
        cp_wait<STAGES - 2>();
        __syncthreads();

        if (kt + STAGES - 1 < KT) load_stage(kt + STAGES - 1, (kt + STAGES - 1) % STAGES);
        cp_commit();

        const int s = kt % STAGES;
        const uint32_t stA = sb + s * SSZ;
        const uint32_t stB = stA + ASZ;

#pragma unroll
        for (int ks = 0; ks < 2; ks++) {
            uint32_t ah[MW][4], bh[NW][2];
#pragma unroll
            for (int i = 0; i < MW; i++)
                ldsm4(ah[i], stA + tile_off(arow[i], 2 * ks + (mat >> 1)));
#pragma unroll
            for (int j = 0; j < NW / 2; j++) {
                uint32_t t[4];
                ldsm4(t, stB + tile_off(brow[j], 2 * ks + (mat & 1)));
                bh[2 * j][0] = t[0]; bh[2 * j][1] = t[1];
                bh[2 * j + 1][0] = t[2]; bh[2 * j + 1][1] = t[3];
            }
#pragma unroll
            for (int i = 0; i < MW; i++)
#pragma unroll
                for (int j = 0; j < NW; j++)
                    mma16816(acc[i][j], ah[i], bh[j]);
        }
    }

    // ---- epilogue ----
    const int lm = lid >> 2, ln2 = (lid & 3) * 2;
#pragma unroll
    for (int i = 0; i < MW; i++)
#pragma unroll
        for (int j = 0; j < NW; j++)
#pragma unroll
            for (int h = 0; h < 2; h++) {
                int gm = row0 + wm0 + i * 16 + h * 8 + lm;
                int gn = col0 + wn0 + j * 8 + ln2;
                float v0 = acc[i][j][2 * h + 0] + __ldg(bias + gn);
                float v1 = acc[i][j][2 * h + 1] + __ldg(bias + gn + 1);
                if (act == 1) { v0 = fmaxf(v0, 0.f); v1 = fmaxf(v1, 0.f); }
                else if (act == 2) {
                    v0 = 1.0f / (1.0f + expf(-v0));
                    v1 = 1.0f / (1.0f + expf(-v1));
                }
                size_t o = (size_t)gm * N + gn;
                if (OUTMODE == 0 || OUTMODE == 2)
                    *reinterpret_cast<float2*>(Cf + o) = make_float2(v0, v1);
                if (OUTMODE == 1 || OUTMODE == 2)
                    *reinterpret_cast<__half2*>(Ch + o) =
                        __halves2half2(__float2half_rn(v0), __float2half_rn(v1));
            }
}

// ---------------------------------------------------------------------------
// Host launch
// ---------------------------------------------------------------------------
extern "C" void kernel_launch(void* const* d_in, const int* in_sizes, int n_in,
                              void* d_out, int out_size) {
    const float* x   = (const float*)d_in[0];
    const float* We1 = (const float*)d_in[1];
    const float* be1 = (const float*)d_in[2];
    const float* We2 = (const float*)d_in[3];
    const float* be2 = (const float*)d_in[4];
    const float* We3 = (const float*)d_in[5];
    const float* be3 = (const float*)d_in[6];
    const float* Wd1 = (const float*)d_in[7];
    const float* bd1 = (const float*)d_in[8];
    const float* Wd2 = (const float*)d_in[9];
    const float* bd2 = (const float*)d_in[10];
    const float* Wd3 = (const float*)d_in[11];
    const float* bd3 = (const float*)d_in[12];

    float* out = (float*)d_out;
    float* control = out;
    float* state   = out + (size_t)BATCH * 64;

    __half *bufA, *bufB, *ctrl, *W;
    cudaGetSymbolAddress((void**)&bufA, g_bufA);
    cudaGetSymbolAddress((void**)&bufB, g_bufB);
    cudaGetSymbolAddress((void**)&ctrl, g_ctrl);
    cudaGetSymbolAddress((void**)&W, g_W);

    // big: 4 stages x (8KB A + 8KB B) = 65536 B -> up to 3 CTAs/SM
    constexpr int SMEM_BIG   = 4 * (128 * 64 + 128 * 64);  // 65536
    constexpr int SMEM_SMALL = 4 * (64 * 64 + 64 * 64);    // 32768
    cudaFuncSetAttribute((const void*)gemm_mma<128,128,4,2,4,3,0>,
                         cudaFuncAttributeMaxDynamicSharedMemorySize, SMEM_BIG);
    cudaFuncSetAttribute((const void*)gemm_mma<128,128,4,2,4,3,1>,
                         cudaFuncAttributeMaxDynamicSharedMemorySize, SMEM_BIG);
    cudaFuncSetAttribute((const void*)gemm_mma<64,64,4,2,4,1,2>,
                         cudaFuncAttributeMaxDynamicSharedMemorySize, SMEM_SMALL);

    // ---- prep: ONE launch (#1) ----
    prep_all<<<dim3(64, 64, 7), dim3(32, 8)>>>(
        x, bufB, We1, We2, We3, Wd1, Wd2, Wd3, W);

    // L1 (#2): x @ We1 -> relu (N=2048, K=1024)
    gemm_mma<128,128,4,2,4,3,1><<<dim3(16, 64), 256, SMEM_BIG>>>(
        bufB, W + OFF_We1, be1, nullptr, bufA, 2048, 1024, 1);
    // L2 (#3): @ We2 -> relu (N=2048, K=2048)
    gemm_mma<128,128,4,2,4,3,1><<<dim3(16, 64), 256, SMEM_BIG>>>(
        bufA, W + OFF_We2, be2, nullptr, bufB, 2048, 2048, 1);
    // L3 (#4): @ We3 -> sigmoid (N=64, K=2048), f32 control + fp16 ctrl
    gemm_mma<64,64,4,2,4,1,2><<<dim3(1, 128), 256, SMEM_SMALL>>>(
        bufB, W + OFF_We3, be3, control, ctrl, 64, 2048, 2);
    // L4 (#5): @ Wd1 -> relu (N=2048, K=64)
    gemm_mma<128,128,4,2,4,3,1><<<dim3(16, 64), 256, SMEM_BIG>>>(
        ctrl, W + OFF_Wd1, bd1, nullptr, bufA, 2048, 64, 1);
    // L5 (#6): @ Wd2 -> relu (N=2048, K=2048)
    gemm_mma<128,128,4,2,4,3,1><<<dim3(16, 64), 256, SMEM_BIG>>>(
        bufA, W + OFF_Wd2, bd2, nullptr, bufB, 2048, 2048, 1);
    // L6 (#7): @ Wd3 -> linear f32 (N=1024, K=2048)
    gemm_mma<128,128,4,2,4,3,0><<<dim3(8, 64), 256, SMEM_BIG>>>(
        bufB, W + OFF_Wd3, bd3, state, nullptr, 1024, 2048, 0);

    (void)in_sizes; (void)n_in; (void)out_size;
}

// round 14
// speedup vs baseline: 1.9352x; 1.9352x over previous
#include <cuda_runtime.h>
#include <cuda_fp16.h>
#include <cstdint>
#include <math.h>

// ============================================================================
// AutoEncoder via mma.sync (HMMA fp16), single fp16 operands, fp32 accum.
// R13: R12 numerics (1 MMA per tile) + R10 occupancy config (MINB=2 ->
//      128-reg budget, no spills, 2 CTAs/SM).
// ============================================================================

#define BATCH 8192

__device__ __forceinline__ uint32_t smem_u32(const void* p) {
    uint32_t a;
    asm("{ .reg .u64 t; cvta.to.shared.u64 t, %1; cvt.u32.u64 %0, t; }"
        : "=r"(a) : "l"(p));
    return a;
}
__device__ __forceinline__ void cp_async16(uint32_t dst, const void* src) {
    asm volatile("cp.async.cg.shared.global [%0], [%1], 16;" :: "r"(dst), "l"(src));
}
__device__ __forceinline__ void cp_commit() {
    asm volatile("cp.async.commit_group;" ::: "memory");
}
template <int N> __device__ __forceinline__ void cp_wait() {
    asm volatile("cp.async.wait_group %0;" :: "n"(N) : "memory");
}
__device__ __forceinline__ void ldsm4(uint32_t* r, uint32_t a) {
    asm volatile("ldmatrix.sync.aligned.m8n8.x4.shared.b16 {%0,%1,%2,%3}, [%4];"
                 : "=r"(r[0]), "=r"(r[1]), "=r"(r[2]), "=r"(r[3]) : "r"(a));
}
__device__ __forceinline__ void mma16816(float* d, const uint32_t* a, const uint32_t* b) {
    asm volatile("mma.sync.aligned.m16n8k16.row.col.f32.f16.f16.f32 "
                 "{%0,%1,%2,%3}, {%4,%5,%6,%7}, {%8,%9}, {%0,%1,%2,%3};"
                 : "+f"(d[0]), "+f"(d[1]), "+f"(d[2]), "+f"(d[3])
                 : "r"(a[0]), "r"(a[1]), "r"(a[2]), "r"(a[3]),
                   "r"(b[0]), "r"(b[1]));
}
// 64B logical rows packed pairwise into 128B atoms + SW128 XOR swizzle.
__device__ __forceinline__ uint32_t tile_off(int r, int c) {
    uint32_t o = ((uint32_t)(r >> 1) << 7) + ((uint32_t)(r & 1) << 6) +
                 ((uint32_t)c << 4);
    return o ^ ((o >> 3) & 0x70);
}

// ---------------------------------------------------------------------------
// Device global scratch
// ---------------------------------------------------------------------------
__device__ __align__(16) __half g_bufA[(size_t)BATCH * 2048];
__device__ __align__(16) __half g_bufB[(size_t)BATCH * 2048];
__device__ __align__(16) __half g_ctrl[(size_t)BATCH * 64];

#define OFF_We1 0u
#define OFF_We2 (OFF_We1 + 2048u*1024u)
#define OFF_We3 (OFF_We2 + 2048u*2048u)
#define OFF_Wd1 (OFF_We3 + 64u*2048u)
#define OFF_Wd2 (OFF_Wd1 + 2048u*64u)
#define OFF_Wd3 (OFF_Wd2 + 2048u*2048u)
#define W_TOTAL (OFF_Wd3 + 1024u*2048u)
__device__ __align__(16) __half g_W[W_TOTAL];

// ---------------------------------------------------------------------------
// Fused prep: ONE launch. z=0: convert x to fp16; z=1..6: transpose weights.
// ---------------------------------------------------------------------------
__global__ void prep_all(const float* __restrict__ x,
                         __half* __restrict__ xh,
                         const float* We1, const float* We2, const float* We3,
                         const float* Wd1, const float* Wd2, const float* Wd3,
                         __half* __restrict__ W)
{
    const int z = blockIdx.z;
    if (z == 0) {
        int tid = threadIdx.y * 32 + threadIdx.x;
        int bid = blockIdx.y * 64 + blockIdx.x;
        int base = (bid * 256 + tid) * 2;
#pragma unroll
        for (int u = 0; u < 2; u++) {
            int i = base + u;
            float4 v = reinterpret_cast<const float4*>(x)[i];
            __half2 p0 = __halves2half2(__float2half_rn(v.x), __float2half_rn(v.y));
            __half2 p1 = __halves2half2(__float2half_rn(v.z), __float2half_rn(v.w));
            reinterpret_cast<__half2*>(xh)[i * 2 + 0] = p0;
            reinterpret_cast<__half2*>(xh)[i * 2 + 1] = p1;
        }
        return;
    }
    const float* Wi; uint32_t off; int K, N;
    switch (z) {
        case 1: Wi = We1; off = OFF_We1; K = 1024; N = 2048; break;
        case 2: Wi = We2; off = OFF_We2; K = 2048; N = 2048; break;
        case 3: Wi = We3; off = OFF_We3; K = 2048; N = 64;   break;
        case 4: Wi = Wd1; off = OFF_Wd1; K = 64;   N = 2048; break;
        case 5: Wi = Wd2; off = OFF_Wd2; K = 2048; N = 2048; break;
        default:Wi = Wd3; off = OFF_Wd3; K = 2048; N = 1024; break;
    }
    int k0 = blockIdx.x * 32, n0 = blockIdx.y * 32;
    if (k0 >= K || n0 >= N) return;
    __shared__ float t[32][33];
    int tx = threadIdx.x, ty = threadIdx.y;
    for (int r = ty; r < 32; r += 8)
        t[r][tx] = Wi[(size_t)(k0 + r) * N + n0 + tx];
    __syncthreads();
    __half* T = W + off;
    for (int r = ty; r < 32; r += 8) {
        size_t o = (size_t)(n0 + r) * K + k0 + tx;
        T[o] = __float2half_rn(t[tx][r]);
    }
}

// ---------------------------------------------------------------------------
// mma.sync fp16 GEMM: C = act(A @ W^T + bias), fp32 accumulate.
// 4-stage ring, 1 sync/iter, MINB CTAs/SM.
// OUTMODE: 0 = f32 only, 1 = fp16 only, 2 = both
// ---------------------------------------------------------------------------
template <int BM, int BN, int WARPS_M, int WARPS_N, int STAGES, int MINB, int OUTMODE>
__global__ __launch_bounds__(WARPS_M * WARPS_N * 32, MINB)
void gemm_mma(const __half* __restrict__ A,
              const __half* __restrict__ B,
              const float* __restrict__ bias,
              float* __restrict__ Cf,
              __half* __restrict__ Ch,
              int N, int K, int act)
{
    constexpr int THREADS = WARPS_M * WARPS_N * 32;
    constexpr int BK = 32;
    constexpr int WM = BM / WARPS_M, WN = BN / WARPS_N;
    constexpr int MW = WM / 16, NW = WN / 8;
    constexpr int ASZ = BM * 64;
    constexpr int BSZ = BN * 64;
    constexpr int SSZ = ASZ + BSZ;

    extern __shared__ __align__(128) char sm[];
    const uint32_t sb = smem_u32(sm);
    const int tid = threadIdx.x, wid = tid >> 5, lid = tid & 31;
    const int row0 = blockIdx.y * BM, col0 = blockIdx.x * BN;
    const int KT = K / BK;

    const int wm0 = (wid % WARPS_M) * WM;
    const int wn0 = (wid / WARPS_M) * WN;
    const int mat = lid >> 3, mr = lid & 7;

    float acc[MW][NW][4];
#pragma unroll
    for (int i = 0; i < MW; i++)
#pragma unroll
        for (int j = 0; j < NW; j++)
#pragma unroll
            for (int q = 0; q < 4; q++) acc[i][j][q] = 0.0f;

    auto load_stage = [&](int kt, int s) {
        const uint32_t st = sb + s * SSZ;
        const int k0 = kt * BK;
#pragma unroll
        for (int ch = tid; ch < BM * 4; ch += THREADS) {
            int r = ch >> 2, c = ch & 3;
            size_t g = (size_t)(row0 + r) * K + k0 + c * 8;
            cp_async16(st + tile_off(r, c), A + g);
        }
#pragma unroll
        for (int ch = tid; ch < BN * 4; ch += THREADS) {
            int r = ch >> 2, c = ch & 3;
            size_t g = (size_t)(col0 + r) * K + k0 + c * 8;
            cp_async16(st + ASZ + tile_off(r, c), B + g);
        }
    };

    int arow[MW], brow[NW / 2];
#pragma unroll
    for (int i = 0; i < MW; i++) arow[i] = wm0 + i * 16 + (mat & 1) * 8 + mr;
#pragma unroll
    for (int j = 0; j < NW / 2; j++) brow[j] = wn0 + j * 16 + (mat >> 1) * 8 + mr;

#pragma unroll
    for (int p = 0; p < STAGES - 1; p++) {
        if (p < KT) load_stage(p, p);
        cp_commit();
    }

    for (int kt = 0; kt < KT; kt++) {
        cp_wait<STAGES - 2>();
        __syncthreads();

        if (kt + STAGES - 1 < KT) load_stage(kt + STAGES - 1, (kt + STAGES - 1) % STAGES);
        cp_commit();

        const int s = kt % STAGES;
        const uint32_t stA = sb + s * SSZ;
        const uint32_t stB = stA + ASZ;

#pragma unroll
        for (int ks = 0; ks < 2; ks++) {
            uint32_t ah[MW][4], bh[NW][2];
#pragma unroll
            for (int i = 0; i < MW; i++)
                ldsm4(ah[i], stA + tile_off(arow[i], 2 * ks + (mat >> 1)));
#pragma unroll
            for (int j = 0; j < NW / 2; j++) {
                uint32_t t[4];
                ldsm4(t, stB + tile_off(brow[j], 2 * ks + (mat & 1)));
                bh[2 * j][0] = t[0]; bh[2 * j][1] = t[1];
                bh[2 * j + 1][0] = t[2]; bh[2 * j + 1][1] = t[3];
            }
#pragma unroll
            for (int i = 0; i < MW; i++)
#pragma unroll
                for (int j = 0; j < NW; j++)
                    mma16816(acc[i][j], ah[i], bh[j]);
        }
    }

    // ---- epilogue ----
    const int lm = lid >> 2, ln2 = (lid & 3) * 2;
#pragma unroll
    for (int i = 0; i < MW; i++)
#pragma unroll
        for (int j = 0; j < NW; j++)
#pragma unroll
            for (int h = 0; h < 2; h++) {
                int gm = row0 + wm0 + i * 16 + h * 8 + lm;
                int gn = col0 + wn0 + j * 8 + ln2;
                float v0 = acc[i][j][2 * h + 0] + __ldg(bias + gn);
                float v1 = acc[i][j][2 * h + 1] + __ldg(bias + gn + 1);
                if (act == 1) { v0 = fmaxf(v0, 0.f); v1 = fmaxf(v1, 0.f); }
                else if (act == 2) {
                    v0 = 1.0f / (1.0f + expf(-v0));
                    v1 = 1.0f / (1.0f + expf(-v1));
                }
                size_t o = (size_t)gm * N + gn;
                if (OUTMODE == 0 || OUTMODE == 2)
                    *reinterpret_cast<float2*>(Cf + o) = make_float2(v0, v1);
                if (OUTMODE == 1 || OUTMODE == 2)
                    *reinterpret_cast<__half2*>(Ch + o) =
                        __halves2half2(__float2half_rn(v0), __float2half_rn(v1));
            }
}

// ---------------------------------------------------------------------------
// Host launch
// ---------------------------------------------------------------------------
extern "C" void kernel_launch(void* const* d_in, const int* in_sizes, int n_in,
                              void* d_out, int out_size) {
    const float* x   = (const float*)d_in[0];
    const float* We1 = (const float*)d_in[1];
    const float* be1 = (const float*)d_in[2];
    const float* We2 = (const float*)d_in[3];
    const float* be2 = (const float*)d_in[4];
    const float* We3 = (const float*)d_in[5];
    const float* be3 = (const float*)d_in[6];
    const float* Wd1 = (const float*)d_in[7];
    const float* bd1 = (const float*)d_in[8];
    const float* Wd2 = (const float*)d_in[9];
    const float* bd2 = (const float*)d_in[10];
    const float* Wd3 = (const float*)d_in[11];
    const float* bd3 = (const float*)d_in[12];

    float* out = (float*)d_out;
    float* control = out;
    float* state   = out + (size_t)BATCH * 64;

    __half *bufA, *bufB, *ctrl, *W;
    cudaGetSymbolAddress((void**)&bufA, g_bufA);
    cudaGetSymbolAddress((void**)&bufB, g_bufB);
    cudaGetSymbolAddress((void**)&ctrl, g_ctrl);
    cudaGetSymbolAddress((void**)&W, g_W);

    // big: 4 stages x 16KB = 64KB smem; MINB=2 -> 128-reg budget (no spill)
    constexpr int SMEM_BIG   = 4 * (128 * 64 + 128 * 64);  // 65536
    constexpr int SMEM_SMALL = 4 * (64 * 64 + 64 * 64);    // 32768
    cudaFuncSetAttribute((const void*)gemm_mma<128,128,4,2,4,2,0>,
                         cudaFuncAttributeMaxDynamicSharedMemorySize, SMEM_BIG);
    cudaFuncSetAttribute((const void*)gemm_mma<128,128,4,2,4,2,1>,
                         cudaFuncAttributeMaxDynamicSharedMemorySize, SMEM_BIG);
    cudaFuncSetAttribute((const void*)gemm_mma<64,64,4,2,4,1,2>,
                         cudaFuncAttributeMaxDynamicSharedMemorySize, SMEM_SMALL);

    // ---- prep: ONE launch (#1) ----
    prep_all<<<dim3(64, 64, 7), dim3(32, 8)>>>(
        x, bufB, We1, We2, We3, Wd1, Wd2, Wd3, W);

    // L1 (#2): x @ We1 -> relu (N=2048, K=1024)
    gemm_mma<128,128,4,2,4,2,1><<<dim3(16, 64), 256, SMEM_BIG>>>(
        bufB, W + OFF_We1, be1, nullptr, bufA, 2048, 1024, 1);
    // L2 (#3): @ We2 -> relu (N=2048, K=2048)
    gemm_mma<128,128,4,2,4,2,1><<<dim3(16, 64), 256, SMEM_BIG>>>(
        bufA, W + OFF_We2, be2, nullptr, bufB, 2048, 2048, 1);
    // L3 (#4): @ We3 -> sigmoid (N=64, K=2048), f32 control + fp16 ctrl
    gemm_mma<64,64,4,2,4,1,2><<<dim3(1, 128), 256, SMEM_SMALL>>>(
        bufB, W + OFF_We3, be3, control, ctrl, 64, 2048, 2);
    // L4 (#5): @ Wd1 -> relu (N=2048, K=64)
    gemm_mma<128,128,4,2,4,2,1><<<dim3(16, 64), 256, SMEM_BIG>>>(
        ctrl, W + OFF_Wd1, bd1, nullptr, bufA, 2048, 64, 1);
    // L5 (#6): @ Wd2 -> relu (N=2048, K=2048)
    gemm_mma<128,128,4,2,4,2,1><<<dim3(16, 64), 256, SMEM_BIG>>>(
        bufA, W + OFF_Wd2, bd2, nullptr, bufB, 2048, 2048, 1);
    // L6 (#7): @ Wd3 -> linear f32 (N=1024, K=2048)
    gemm_mma<128,128,4,2,4,2,0><<<dim3(8, 64), 256, SMEM_BIG>>>(
        bufB, W + OFF_Wd3, bd3, state, nullptr, 1024, 2048, 0);

    (void)in_sizes; (void)n_in; (void)out_size;
}